// round 14
// baseline (speedup 1.0000x reference)
#include <cuda_runtime.h>
#include <cuda_bf16.h>
#include <cuda_fp16.h>
#include <cstdint>

#define B_  4
#define S_  1024
#define D_  512
#define H_  8
#define DK_ 64
#define MTOT (B_*S_)          // 4096 rows
#define NELE (B_*S_*D_)       // 2,097,152
#define DD   (D_*D_)
#define LOG2E 1.4426950408889634f

// Scratch (static device globals — allowed; no cudaMalloc anywhere)
__device__ __half g_in_h[(size_t)3*NELE];   // Q,K,V inputs fp16 (single plane)
__device__ __half g_w_h[4*DD];              // Wq,Wk,Wv,Wo fp16
__device__ __half g_oh[NELE], g_ol[NELE];   // attn out fp16 hi/lo
__device__ __half g_qh[NELE];   // projected Q (pre-scaled by log2e/8), fp16
__device__ __half g_kh[NELE];   // projected K, fp16
__device__ __half g_vh[NELE];   // projected V, fp16
__device__ float g_bias[(size_t)B_*S_*S_];  // bias*log2e, mask folded as -1.5e9
__device__ float g_Ct, g_Cd;
__device__ int   g_bzero;

// ---------------------------------------------------------------------------
// helpers
// ---------------------------------------------------------------------------
__device__ __forceinline__ float ex2f(float x) {
    float r; asm("ex2.approx.f32 %0, %1;" : "=f"(r) : "f"(x)); return r;
}

__device__ __forceinline__ void mma_f16(float c[4],
    uint32_t a0, uint32_t a1, uint32_t a2, uint32_t a3,
    uint32_t b0, uint32_t b1)
{
    asm volatile(
        "mma.sync.aligned.m16n8k16.row.col.f32.f16.f16.f32 "
        "{%0,%1,%2,%3},{%4,%5,%6,%7},{%8,%9},{%0,%1,%2,%3};"
        : "+f"(c[0]), "+f"(c[1]), "+f"(c[2]), "+f"(c[3])
        : "r"(a0), "r"(a1), "r"(a2), "r"(a3), "r"(b0), "r"(b1));
}

__device__ __forceinline__ void ldsm_x4(uint32_t& r0, uint32_t& r1,
                                        uint32_t& r2, uint32_t& r3, uint32_t addr)
{
    asm volatile("ldmatrix.sync.aligned.m8n8.x4.shared.b16 {%0,%1,%2,%3}, [%4];"
        : "=r"(r0), "=r"(r1), "=r"(r2), "=r"(r3) : "r"(addr));
}

__device__ __forceinline__ void ldsm_x4_t(uint32_t& r0, uint32_t& r1,
                                          uint32_t& r2, uint32_t& r3, uint32_t addr)
{
    asm volatile("ldmatrix.sync.aligned.m8n8.x4.trans.shared.b16 {%0,%1,%2,%3}, [%4];"
        : "=r"(r0), "=r"(r1), "=r"(r2), "=r"(r3) : "r"(addr));
}

__device__ __forceinline__ void cpa16(uint32_t dst, const void* src) {
    asm volatile("cp.async.cg.shared.global [%0], [%1], 16;" :: "r"(dst), "l"(src));
}
__device__ __forceinline__ void cp_commit() {
    asm volatile("cp.async.commit_group;");
}
template<int N> __device__ __forceinline__ void cp_wait() {
    asm volatile("cp.async.wait_group %0;" :: "n"(N));
}

// fp16 hi/lo split pack of a float pair
__device__ __forceinline__ void pack_hilo_h(float x, float y, uint32_t& hi, uint32_t& lo) {
    __half2 h = __floats2half2_rn(x, y);
    float2 f = __half22float2(h);
    __half2 l = __floats2half2_rn(x - f.x, y - f.y);
    hi = *reinterpret_cast<uint32_t*>(&h);
    lo = *reinterpret_cast<uint32_t*>(&l);
}

// ---------------------------------------------------------------------------
// Split fp32 tensors -> single fp16 plane. Last block also runs the prep.
// ---------------------------------------------------------------------------
#define IN_BLKS (NELE/1024)      // 2048 per tensor
#define W_BLKS  (DD/1024)        // 256 per tensor
#define SPLIT_BLKS (3*IN_BLKS + 4*W_BLKS + 1)

__global__ __launch_bounds__(256) void split_all(
    const float* __restrict__ Q, const float* __restrict__ K, const float* __restrict__ V,
    const float* __restrict__ Wq, const float* __restrict__ Wk,
    const float* __restrict__ Wv, const float* __restrict__ Wo,
    __half* __restrict__ inh, __half* __restrict__ wh,
    const float* __restrict__ tm_w, const float* __restrict__ tm_b,
    const float* __restrict__ dm_w, const float* __restrict__ dm_b,
    const float* __restrict__ td_w)
{
    const int bx = blockIdx.x;
    if (bx == SPLIT_BLKS - 1) {               // prep block
        const int l = threadIdx.x;
        if (l < 32) {
            float ct = 0.f, cd = 0.f;
            bool z = true;
            #pragma unroll
            for (int m = l; m < 64; m += 32) {
                z = z && (tm_b[m] == 0.f) && (dm_b[m] == 0.f);
                ct += (0.5f * LOG2E) * td_w[m] * fmaxf(tm_w[m], 0.f);
                cd += (0.5f * LOG2E) * td_w[m] * fmaxf(dm_w[m], 0.f);
            }
            unsigned bz = __ballot_sync(0xffffffffu, z);
            #pragma unroll
            for (int o = 16; o; o >>= 1) {
                ct += __shfl_xor_sync(0xffffffffu, ct, o);
                cd += __shfl_xor_sync(0xffffffffu, cd, o);
            }
            if (l == 0) { g_Ct = ct; g_Cd = cd; g_bzero = (bz == 0xffffffffu); }
        }
        return;
    }

    const float* s;
    __half* dst;
    size_t off;
    if (bx < 3 * IN_BLKS) {
        int ten = bx / IN_BLKS, rel = bx % IN_BLKS;
        s = ((ten == 0) ? Q : (ten == 1) ? K : V) + (size_t)rel * 1024;
        off = (size_t)ten * NELE + (size_t)rel * 1024;
        dst = inh;
    } else {
        int id = bx - 3 * IN_BLKS;
        int ten = id / W_BLKS, rel = id % W_BLKS;
        s = ((ten == 0) ? Wq : (ten == 1) ? Wk : (ten == 2) ? Wv : Wo)
            + (size_t)rel * 1024;
        off = (size_t)ten * DD + (size_t)rel * 1024;
        dst = wh;
    }
    const size_t si = (size_t)threadIdx.x * 4;
    float4 v = *(const float4*)&s[si];
    __half2 h01 = __floats2half2_rn(v.x, v.y);
    __half2 h23 = __floats2half2_rn(v.z, v.w);
    *(uint2*)&dst[off + si] = make_uint2(*(uint32_t*)&h01, *(uint32_t*)&h23);
}

// ---------------------------------------------------------------------------
// Templated GEMM: tile MT x 128, A fp16 (+ lo plane if TWO), 3-stage cp.async
// pipeline. MT=128: 8 warps 4m x 2n; MT=64: 8 warps 2m x 4n.
// For MT=128, blockIdx.z in 3..6 runs co-scheduled bias+mask CTAs.
// ---------------------------------------------------------------------------
#define AKP 40
#define BNP 136
#define BS (32*BNP)

template<int MT, bool TWO>
__global__ __launch_bounds__(256, 2) void gemm_planes(
    const __half* __restrict__ Ah_, const __half* __restrict__ Al_,
    const __half* __restrict__ Wh_,
    size_t aStride, size_t wStride,
    const float* __restrict__ b0v, const float* __restrict__ b1v, const float* __restrict__ b2v,
    float* __restrict__ C0,
    __half* __restrict__ H0, __half* __restrict__ H1, __half* __restrict__ H2,
    int M, int N, int K, float scale0, int fp16_out,
    const float* __restrict__ tmat, const float* __restrict__ dmat,
    const int*   __restrict__ mask,
    const float* __restrict__ tm_w, const float* __restrict__ tm_b,
    const float* __restrict__ dm_w, const float* __restrict__ dm_b,
    const float* __restrict__ td_w, const float* __restrict__ td_b)
{
    extern __shared__ __half gsm[];
    const int t = threadIdx.x;

    // =================== bias + mask CTAs (MT=128 launch only) ============
    if (MT == 128 && blockIdx.z >= 3) {
        const int cta = (blockIdx.z - 3) * 128 + blockIdx.y * 4 + blockIdx.x; // 0..511
        const float tdb = td_b[0] * LOG2E;
        const float E = 2.718281828459045f;
        const int bz = g_bzero;
        const float Ct = g_Ct, Cd = g_Cd;

        float* sp = (float*)gsm;
        if (!bz) {
            if (t < 64) {
                sp[0*64 + t] = tm_w[t];
                sp[1*64 + t] = tm_b[t];
                sp[2*64 + t] = dm_w[t];
                sp[3*64 + t] = dm_b[t];
                sp[4*64 + t] = td_w[t] * 0.5f * LOG2E;
            }
            __syncthreads();
        }

        #pragma unroll 2
        for (int i = 0; i < 8; i++) {
            const size_t base = (((size_t)cta * 8 + i) * 256 + t) * 4;
            float4 u  = *(const float4*)(tmat + base);
            float4 w4 = *(const float4*)(dmat + base);
            int4   mk = *(const int4*)(mask + base);

            float tv[4] = { 1.f / __logf(E + u.x), 1.f / __logf(E + u.y),
                            1.f / __logf(E + u.z), 1.f / __logf(E + u.w) };
            float dv[4] = { 1.f / __logf(E + w4.x), 1.f / __logf(E + w4.y),
                            1.f / __logf(E + w4.z), 1.f / __logf(E + w4.w) };
            float acc[4];
            if (bz) {
                #pragma unroll
                for (int e = 0; e < 4; e++)
                    acc[e] = fmaf(tv[e], Ct, fmaf(dv[e], Cd, tdb));
            } else {
                #pragma unroll
                for (int e = 0; e < 4; e++) acc[e] = tdb;
                #pragma unroll 8
                for (int m = 0; m < 64; m++) {
                    const float tw = sp[0*64 + m], tb = sp[1*64 + m];
                    const float dw = sp[2*64 + m], db = sp[3*64 + m];
                    const float ww = sp[4*64 + m];
                    #pragma unroll
                    for (int e = 0; e < 4; e++) {
                        float rt = fmaxf(tv[e] * tw + tb, 0.f);
                        float rd = fmaxf(dv[e] * dw + db, 0.f);
                        acc[e] += ww * (rt + rd);
                    }
                }
            }
            float4 o;
            o.x = (mk.x == 1) ? -1.5e9f : acc[0];
            o.y = (mk.y == 1) ? -1.5e9f : acc[1];
            o.z = (mk.z == 1) ? -1.5e9f : acc[2];
            o.w = (mk.w == 1) ? -1.5e9f : acc[3];
            *(float4*)(g_bias + base) = o;
        }
        return;
    }

    // =================== GEMM CTAs ===================
    constexpr int AS = MT * AKP;
    constexpr int WM = (MT == 128) ? 4 : 2;      // m-warps
    constexpr int NP = WM;                        // 16-wide n p-tiles per warp
    __half* Ahs = gsm;                            // [3][AS]
    __half* Als = TWO ? gsm + 3 * AS : nullptr;   // [3][AS]
    __half* Bhs = gsm + (TWO ? 6 : 3) * AS;       // [3][BS]

    const int z = blockIdx.z;
    const __half* Ah = Ah_ + (size_t)z * aStride;
    const __half* Al = TWO ? (Al_ + (size_t)z * aStride) : nullptr;
    const __half* Wh = Wh_ + (size_t)z * wStride;
    const float* bias = (z == 0) ? b0v : (z == 1) ? b1v : b2v;
    __half* Ho = (z == 0) ? H0 : (z == 1) ? H1 : H2;
    const float osc = (z == 0) ? scale0 : 1.f;

    const int lane = t & 31, wid = t >> 5;
    const int warp_m = wid & (WM - 1), warp_n = wid / WM;
    const int m_w = warp_m * 32, n_w = warp_n * (16 * WM);
    const int bm = blockIdx.y * MT, bn = blockIdx.x * 128;
    const int gid = lane >> 2, tig = lane & 3;
    const int m_idx = lane >> 3, rin = lane & 7;

    float acc[2][2 * NP][4];
    #pragma unroll
    for (int mt = 0; mt < 2; mt++)
        #pragma unroll
        for (int nt = 0; nt < 2 * NP; nt++)
            #pragma unroll
            for (int e = 0; e < 4; e++) acc[mt][nt][e] = 0.f;

    auto issue = [&](int st, int k0) {
        #pragma unroll
        for (int r = 0; r < MT / 64; r++) {
            int c = t + r * 256;
            int arow = c >> 2, ak = (c & 3) * 8;
            size_t ga = (size_t)(bm + arow) * K + k0 + ak;
            cpa16((uint32_t)__cvta_generic_to_shared(&Ahs[st * AS + arow * AKP + ak]), &Ah[ga]);
            if (TWO)
                cpa16((uint32_t)__cvta_generic_to_shared(&Als[st * AS + arow * AKP + ak]), &Al[ga]);
        }
        #pragma unroll
        for (int r = 0; r < 2; r++) {
            int c = t + r * 256;
            int krow = c >> 4, nc = (c & 15) * 8;
            size_t gb = (size_t)(k0 + krow) * N + bn + nc;
            cpa16((uint32_t)__cvta_generic_to_shared(&Bhs[st * BS + krow * BNP + nc]), &Wh[gb]);
        }
    };

    // 3-stage pipeline prologue
    issue(0, 0);
    cp_commit();
    issue(1, 32);
    cp_commit();

    const int NIT = K / 32;
    int st = 0;
    for (int it = 0; it < NIT; it++) {
        if (it + 2 < NIT) {
            int s2 = st + 2; if (s2 >= 3) s2 -= 3;
            issue(s2, (it + 2) * 32);
            cp_commit();
            cp_wait<2>();
        } else if (it + 1 < NIT) {
            cp_wait<1>();
        } else {
            cp_wait<0>();
        }
        __syncthreads();

        #pragma unroll
        for (int kb = 0; kb < 32; kb += 16) {
            uint32_t af[2][2][4];
            #pragma unroll
            for (int mt = 0; mt < 2; mt++) {
                const int arow = m_w + mt * 16 + (lane & 15);
                const int acol = kb + ((lane >> 4) << 3);
                ldsm_x4(af[mt][0][0], af[mt][0][1], af[mt][0][2], af[mt][0][3],
                        (uint32_t)__cvta_generic_to_shared(&Ahs[st * AS + arow * AKP + acol]));
                if (TWO)
                    ldsm_x4(af[mt][1][0], af[mt][1][1], af[mt][1][2], af[mt][1][3],
                            (uint32_t)__cvta_generic_to_shared(&Als[st * AS + arow * AKP + acol]));
            }
            #pragma unroll
            for (int p = 0; p < NP; p++) {
                const int brow = kb + ((m_idx & 1) << 3) + rin;
                const int bcol = n_w + p * 16 + ((m_idx >> 1) << 3);
                uint32_t bh0, bh1, bh2, bh3;
                ldsm_x4_t(bh0, bh1, bh2, bh3,
                    (uint32_t)__cvta_generic_to_shared(&Bhs[st * BS + brow * BNP + bcol]));
                #pragma unroll
                for (int mt = 0; mt < 2; mt++) {
                    mma_f16(acc[mt][2*p], af[mt][0][0], af[mt][0][1],
                            af[mt][0][2], af[mt][0][3], bh0, bh1);
                    mma_f16(acc[mt][2*p+1], af[mt][0][0], af[mt][0][1],
                            af[mt][0][2], af[mt][0][3], bh2, bh3);
                    if (TWO) {
                        mma_f16(acc[mt][2*p], af[mt][1][0], af[mt][1][1],
                                af[mt][1][2], af[mt][1][3], bh0, bh1);
                        mma_f16(acc[mt][2*p+1], af[mt][1][0], af[mt][1][1],
                                af[mt][1][2], af[mt][1][3], bh2, bh3);
                    }
                }
            }
        }
        __syncthreads();
        st = (st + 1 == 3) ? 0 : st + 1;
    }

    // ---- epilogue
    #pragma unroll
    for (int mt = 0; mt < 2; mt++) {
        const int row0 = bm + m_w + mt * 16 + gid;
        #pragma unroll
        for (int nt = 0; nt < 2 * NP; nt++) {
            const int col = bn + n_w + nt * 8 + tig * 2;
            float2 bb = *(const float2*)&bias[col];
            float v0 = (acc[mt][nt][0] + bb.x) * osc;
            float v1 = (acc[mt][nt][1] + bb.y) * osc;
            float v2 = (acc[mt][nt][2] + bb.x) * osc;
            float v3 = (acc[mt][nt][3] + bb.y) * osc;
            if (fp16_out) {
                __half2 h01 = __floats2half2_rn(v0, v1);
                __half2 h23 = __floats2half2_rn(v2, v3);
                *(__half2*)&Ho[(size_t)row0 * N + col]       = h01;
                *(__half2*)&Ho[(size_t)(row0 + 8) * N + col] = h23;
            } else {
                *(float2*)&C0[(size_t)row0 * N + col]       = make_float2(v0, v1);
                *(float2*)&C0[(size_t)(row0 + 8) * N + col] = make_float2(v2, v3);
            }
        }
    }
}

#define GSMEM_QKV ((3*(128*AKP) + 3*BS) * 2)   // 56832 B
#define GSMEM_O   ((6*(64*AKP)  + 3*BS) * 2)   // 56832 B

// ---------------------------------------------------------------------------
// Flash attention, pure fp16 TC, log2-domain softmax. Bias staged warp-local
// (each warp copies exactly the 16 rows it reads) -> mid-iteration barrier is
// only __syncwarp(). KV double-buffered as before.
// ---------------------------------------------------------------------------
#define PS 72
#define PE (64*PS)
#define BSS 68
#define KV0 8704
#define SMEM_ATTN ((KV0 + 4*PE)*2)   // 54272 bytes

__global__ __launch_bounds__(128, 4) void attn_f16()
{
    extern __shared__ __half sm[];
    float* biasS = (float*)sm;

    const int qt = blockIdx.x, h = blockIdx.y, b = blockIdx.z;
    const int t = threadIdx.x;
    const int w = t >> 5, lane = t & 31;
    const int gid = lane >> 2, tig = lane & 3;
    const int q0 = qt * 64, hoff = h * DK_;
    const int tr = w * 16 + gid;
    const int m_idx = lane >> 3, rin = lane & 7;

    #pragma unroll
    for (int i = 0; i < 4; i++) {
        int c = t + i * 128;
        int row = c >> 3, col = (c & 7) * 8;
        size_t gq = (size_t)(b * S_ + q0 + row) * D_ + hoff + col;
        size_t gk = (size_t)(b * S_ + row) * D_ + hoff + col;
        uint32_t so = row * PS + col;
        cpa16((uint32_t)__cvta_generic_to_shared(&sm[so]),            &g_qh[gq]);
        cpa16((uint32_t)__cvta_generic_to_shared(&sm[KV0 + so]),      &g_kh[gk]);
        cpa16((uint32_t)__cvta_generic_to_shared(&sm[KV0 + PE + so]), &g_vh[gk]);
    }
    cp_commit();
    cp_wait<0>();
    __syncthreads();

    uint32_t qf[4][4];
    #pragma unroll
    for (int d8 = 0; d8 < 4; d8++) {
        uint32_t a = (uint32_t)__cvta_generic_to_shared(
            &sm[(w * 16 + (lane & 15)) * PS + d8 * 16 + ((lane >> 4) << 3)]);
        ldsm_x4(qf[d8][0], qf[d8][1], qf[d8][2], qf[d8][3], a);
    }
    __syncthreads();   // Q plane dead -> bias buffer

    float m0 = -1e30f, m1 = -1e30f, l0 = 0.f, l1 = 0.f;
    float oacc[8][4];
    #pragma unroll
    for (int nt = 0; nt < 8; nt++)
        #pragma unroll
        for (int e = 0; e < 4; e++) oacc[nt][e] = 0.f;

    for (int kt = 0; kt < 16; kt++) {
        const int buf = kt & 1;

        // ---- issue bias(kt), warp-local rows [16w, 16w+16)
        #pragma unroll
        for (int i = 0; i < 8; i++) {
            int idx = lane + i * 32;                 // 0..255 within warp block
            int row = w * 16 + (idx >> 4);
            int c4 = (idx & 15) * 4;
            cpa16((uint32_t)__cvta_generic_to_shared(&biasS[row * BSS + c4]),
                  &g_bias[((size_t)(b * S_ + q0 + row)) * S_ + kt * 64 + c4]);
        }
        cp_commit();

        // ---- issue KV(kt+1), wait KV(kt)
        if (kt < 15) {
            const int k1 = (kt + 1) * 64;
            const int KBn = KV0 + (buf ^ 1) * 2 * PE;
            #pragma unroll
            for (int i = 0; i < 4; i++) {
                int c = t + i * 128;
                int row = c >> 3, col = (c & 7) * 8;
                size_t g = (size_t)(b * S_ + k1 + row) * D_ + hoff + col;
                uint32_t so = row * PS + col;
                cpa16((uint32_t)__cvta_generic_to_shared(&sm[KBn + so]),      &g_kh[g]);
                cpa16((uint32_t)__cvta_generic_to_shared(&sm[KBn + PE + so]), &g_vh[g]);
            }
            cp_commit();
            cp_wait<2>();
        } else {
            cp_wait<1>();
        }
        __syncthreads();

        const int KB = KV0 + buf * 2 * PE;

        // ---- scores S = Q @ K^T (log2-domain), single-term fp16
        float sacc[8][4];
        #pragma unroll
        for (int nt = 0; nt < 8; nt++)
            #pragma unroll
            for (int e = 0; e < 4; e++) sacc[nt][e] = 0.f;

        #pragma unroll
        for (int d8 = 0; d8 < 4; d8++) {
            #pragma unroll
            for (int p = 0; p < 4; p++) {
                uint32_t boff = (p * 16 + ((m_idx & 1) << 3) + rin) * PS
                              + d8 * 16 + ((m_idx >> 1) << 3);
                uint32_t kh0, kh1, kh2, kh3;
                ldsm_x4(kh0, kh1, kh2, kh3,
                        (uint32_t)__cvta_generic_to_shared(&sm[KB + boff]));
                mma_f16(sacc[2*p],   qf[d8][0], qf[d8][1], qf[d8][2], qf[d8][3], kh0, kh2);
                mma_f16(sacc[2*p+1], qf[d8][0], qf[d8][1], qf[d8][2], qf[d8][3], kh1, kh3);
            }
        }

        // ---- bias resident (warp-local): wait own groups + syncwarp
        if (kt < 15) { cp_wait<1>(); } else { cp_wait<0>(); }
        __syncwarp();

        float mx0 = -1e30f, mx1 = -1e30f;
        #pragma unroll
        for (int nt = 0; nt < 8; nt++) {
            float2 ba = *(const float2*)&biasS[tr * BSS + nt * 8 + tig * 2];
            float2 bb = *(const float2*)&biasS[(tr + 8) * BSS + nt * 8 + tig * 2];
            sacc[nt][0] += ba.x;
            sacc[nt][1] += ba.y;
            sacc[nt][2] += bb.x;
            sacc[nt][3] += bb.y;
            mx0 = fmaxf(mx0, fmaxf(sacc[nt][0], sacc[nt][1]));
            mx1 = fmaxf(mx1, fmaxf(sacc[nt][2], sacc[nt][3]));
        }
        mx0 = fmaxf(mx0, __shfl_xor_sync(0xffffffffu, mx0, 1));
        mx0 = fmaxf(mx0, __shfl_xor_sync(0xffffffffu, mx0, 2));
        mx1 = fmaxf(mx1, __shfl_xor_sync(0xffffffffu, mx1, 1));
        mx1 = fmaxf(mx1, __shfl_xor_sync(0xffffffffu, mx1, 2));

        const float mn0 = fmaxf(m0, mx0), mn1 = fmaxf(m1, mx1);
        const float c0 = ex2f(m0 - mn0), c1 = ex2f(m1 - mn1);
        m0 = mn0; m1 = mn1;

        float rs0 = 0.f, rs1 = 0.f;
        #pragma unroll
        for (int nt = 0; nt < 8; nt++) {
            sacc[nt][0] = ex2f(sacc[nt][0] - mn0);
            sacc[nt][1] = ex2f(sacc[nt][1] - mn0);
            sacc[nt][2] = ex2f(sacc[nt][2] - mn1);
            sacc[nt][3] = ex2f(sacc[nt][3] - mn1);
            rs0 += sacc[nt][0] + sacc[nt][1];
            rs1 += sacc[nt][2] + sacc[nt][3];
        }
        rs0 += __shfl_xor_sync(0xffffffffu, rs0, 1);
        rs0 += __shfl_xor_sync(0xffffffffu, rs0, 2);
        rs1 += __shfl_xor_sync(0xffffffffu, rs1, 1);
        rs1 += __shfl_xor_sync(0xffffffffu, rs1, 2);

        l0 = l0 * c0 + rs0;
        l1 = l1 * c1 + rs1;
        #pragma unroll
        for (int nt = 0; nt < 8; nt++) {
            oacc[nt][0] *= c0; oacc[nt][1] *= c0;
            oacc[nt][2] *= c1; oacc[nt][3] *= c1;
        }

        uint32_t pa[4][4];
        #pragma unroll
        for (int j8 = 0; j8 < 4; j8++) {
            const float* sA = sacc[2 * j8];
            const float* sB = sacc[2 * j8 + 1];
            __half2 hh;
            hh = __floats2half2_rn(sA[0], sA[1]); pa[j8][0] = *(uint32_t*)&hh;
            hh = __floats2half2_rn(sA[2], sA[3]); pa[j8][1] = *(uint32_t*)&hh;
            hh = __floats2half2_rn(sB[0], sB[1]); pa[j8][2] = *(uint32_t*)&hh;
            hh = __floats2half2_rn(sB[2], sB[3]); pa[j8][3] = *(uint32_t*)&hh;
        }

        #pragma unroll
        for (int j8 = 0; j8 < 4; j8++) {
            #pragma unroll
            for (int p = 0; p < 4; p++) {
                uint32_t boff = (j8 * 16 + ((m_idx & 1) << 3) + rin) * PS
                              + p * 16 + ((m_idx >> 1) << 3);
                uint32_t vh0, vh1, vh2, vh3;
                ldsm_x4_t(vh0, vh1, vh2, vh3,
                          (uint32_t)__cvta_generic_to_shared(&sm[KB + PE + boff]));
                mma_f16(oacc[2*p],   pa[j8][0], pa[j8][1], pa[j8][2], pa[j8][3], vh0, vh1);
                mma_f16(oacc[2*p+1], pa[j8][0], pa[j8][1], pa[j8][2], pa[j8][3], vh2, vh3);
            }
        }
        __syncthreads();   // KV buf reads done before refill; orders bias WAR too
    }

    const float inv0 = 1.f / l0, inv1 = 1.f / l1;
    const size_t o0 = (size_t)(b * S_ + q0 + tr) * D_ + hoff;
    const size_t o1 = o0 + (size_t)8 * D_;
    #pragma unroll
    for (int nt = 0; nt < 8; nt++) {
        const int coff = nt * 8 + tig * 2;
        uint32_t h01, l01, h23, l23;
        pack_hilo_h(oacc[nt][0] * inv0, oacc[nt][1] * inv0, h01, l01);
        pack_hilo_h(oacc[nt][2] * inv1, oacc[nt][3] * inv1, h23, l23);
        *(uint32_t*)&g_oh[o0 + coff] = h01;
        *(uint32_t*)&g_ol[o0 + coff] = l01;
        *(uint32_t*)&g_oh[o1 + coff] = h23;
        *(uint32_t*)&g_ol[o1 + coff] = l23;
    }
}

// ---------------------------------------------------------------------------
extern "C" void kernel_launch(void* const* d_in, const int* in_sizes, int n_in,
                              void* d_out, int out_size)
{
    const float* Q     = (const float*)d_in[0];
    const float* K     = (const float*)d_in[1];
    const float* V     = (const float*)d_in[2];
    const float* tmat  = (const float*)d_in[3];
    const float* dmat  = (const float*)d_in[4];
    const int*   mask  = (const int*)  d_in[5];
    const float* Wq    = (const float*)d_in[6];
    const float* bq    = (const float*)d_in[7];
    const float* Wk    = (const float*)d_in[8];
    const float* bk    = (const float*)d_in[9];
    const float* Wv    = (const float*)d_in[10];
    const float* bv    = (const float*)d_in[11];
    const float* Wo    = (const float*)d_in[12];
    const float* bo    = (const float*)d_in[13];
    const float* tm_w  = (const float*)d_in[14];
    const float* tm_b  = (const float*)d_in[15];
    const float* dm_w  = (const float*)d_in[16];
    const float* dm_b  = (const float*)d_in[17];
    const float* td_w  = (const float*)d_in[18];
    const float* td_b  = (const float*)d_in[19];
    float* out = (float*)d_out;

    __half *inh, *wh, *oh, *ol, *qh, *kh, *vh;
    cudaGetSymbolAddress((void**)&inh, g_in_h);
    cudaGetSymbolAddress((void**)&wh,  g_w_h);
    cudaGetSymbolAddress((void**)&oh,  g_oh);
    cudaGetSymbolAddress((void**)&ol,  g_ol);
    cudaGetSymbolAddress((void**)&qh,  g_qh);
    cudaGetSymbolAddress((void**)&kh,  g_kh);
    cudaGetSymbolAddress((void**)&vh,  g_vh);

    // split inputs/weights to fp16 + prep coefficients, one launch
    split_all<<<SPLIT_BLKS, 256>>>(
        Q, K, V, Wq, Wk, Wv, Wo, inh, wh, tm_w, tm_b, dm_w, dm_b, td_w);

    cudaFuncSetAttribute(gemm_planes<128, false>,
                         cudaFuncAttributeMaxDynamicSharedMemorySize, GSMEM_QKV);
    cudaFuncSetAttribute(gemm_planes<64, true>,
                         cudaFuncAttributeMaxDynamicSharedMemorySize, GSMEM_O);

    // fused Q/K/V projections (z=0..2) + bias/mask CTAs (z=3..6) in ONE launch
    gemm_planes<128, false><<<dim3(D_ / 128, MTOT / 128, 7), 256, GSMEM_QKV>>>(
        inh, nullptr, wh, (size_t)NELE, (size_t)DD,
        bq, bk, bv,
        out /*unused*/, qh, kh, vh,
        MTOT, D_, D_, 0.125f * LOG2E, 1,
        tmat, dmat, mask, tm_w, tm_b, dm_w, dm_b, td_w, td_b);

    cudaFuncSetAttribute(attn_f16,
                         cudaFuncAttributeMaxDynamicSharedMemorySize, SMEM_ATTN);
    attn_f16<<<dim3(S_ / 64, H_, B_), 128, SMEM_ATTN>>>();

    // output projection: fp16 hi/lo A (attn out), 64x128 tiles -> 256 CTAs
    gemm_planes<64, true><<<dim3(D_ / 128, MTOT / 64, 1), 256, GSMEM_O>>>(
        oh, ol, wh + (size_t)3 * DD, 0, 0,
        bo, bo, bo,
        out, qh, kh, vh,
        MTOT, D_, D_, 1.f, 0,
        tmat, dmat, mask, tm_w, tm_b, dm_w, dm_b, td_w, td_b);
}

// round 17
// speedup vs baseline: 1.0669x; 1.0669x over previous
#include <cuda_runtime.h>
#include <cuda_bf16.h>
#include <cuda_fp16.h>
#include <cstdint>

#define B_  4
#define S_  1024
#define D_  512
#define H_  8
#define DK_ 64
#define MTOT (B_*S_)          // 4096 rows
#define NELE (B_*S_*D_)       // 2,097,152
#define DD   (D_*D_)
#define LOG2E 1.4426950408889634f

// Scratch (static device globals — allowed; no cudaMalloc anywhere)
__device__ __half g_in_h[(size_t)3*NELE];   // Q,K,V inputs fp16 (single plane)
__device__ __half g_w_h[4*DD];              // Wq,Wk,Wv,Wo fp16
__device__ __half g_oh[NELE];               // attn out fp16 (single plane)
__device__ __half g_qh[NELE];   // projected Q (pre-scaled by log2e/8), fp16
__device__ __half g_kh[NELE];   // projected K, fp16
__device__ __half g_vh[NELE];   // projected V, fp16
__device__ float g_bias[(size_t)B_*S_*S_];  // bias*log2e, mask folded as -1.5e9
__device__ float g_Ct, g_Cd;
__device__ int   g_bzero;

// ---------------------------------------------------------------------------
// helpers
// ---------------------------------------------------------------------------
__device__ __forceinline__ float ex2f(float x) {
    float r; asm("ex2.approx.f32 %0, %1;" : "=f"(r) : "f"(x)); return r;
}

__device__ __forceinline__ void mma_f16(float c[4],
    uint32_t a0, uint32_t a1, uint32_t a2, uint32_t a3,
    uint32_t b0, uint32_t b1)
{
    asm volatile(
        "mma.sync.aligned.m16n8k16.row.col.f32.f16.f16.f32 "
        "{%0,%1,%2,%3},{%4,%5,%6,%7},{%8,%9},{%0,%1,%2,%3};"
        : "+f"(c[0]), "+f"(c[1]), "+f"(c[2]), "+f"(c[3])
        : "r"(a0), "r"(a1), "r"(a2), "r"(a3), "r"(b0), "r"(b1));
}

__device__ __forceinline__ void ldsm_x4(uint32_t& r0, uint32_t& r1,
                                        uint32_t& r2, uint32_t& r3, uint32_t addr)
{
    asm volatile("ldmatrix.sync.aligned.m8n8.x4.shared.b16 {%0,%1,%2,%3}, [%4];"
        : "=r"(r0), "=r"(r1), "=r"(r2), "=r"(r3) : "r"(addr));
}

__device__ __forceinline__ void ldsm_x4_t(uint32_t& r0, uint32_t& r1,
                                          uint32_t& r2, uint32_t& r3, uint32_t addr)
{
    asm volatile("ldmatrix.sync.aligned.m8n8.x4.trans.shared.b16 {%0,%1,%2,%3}, [%4];"
        : "=r"(r0), "=r"(r1), "=r"(r2), "=r"(r3) : "r"(addr));
}

__device__ __forceinline__ void cpa16(uint32_t dst, const void* src) {
    asm volatile("cp.async.cg.shared.global [%0], [%1], 16;" :: "r"(dst), "l"(src));
}
__device__ __forceinline__ void cp_commit() {
    asm volatile("cp.async.commit_group;");
}
template<int N> __device__ __forceinline__ void cp_wait() {
    asm volatile("cp.async.wait_group %0;" :: "n"(N));
}

// ---------------------------------------------------------------------------
// Split fp32 tensors -> single fp16 plane. Last block also runs the prep.
// ---------------------------------------------------------------------------
#define IN_BLKS (NELE/1024)      // 2048 per tensor
#define W_BLKS  (DD/1024)        // 256 per tensor
#define SPLIT_BLKS (3*IN_BLKS + 4*W_BLKS + 1)

__global__ __launch_bounds__(256) void split_all(
    const float* __restrict__ Q, const float* __restrict__ K, const float* __restrict__ V,
    const float* __restrict__ Wq, const float* __restrict__ Wk,
    const float* __restrict__ Wv, const float* __restrict__ Wo,
    __half* __restrict__ inh, __half* __restrict__ wh,
    const float* __restrict__ tm_w, const float* __restrict__ tm_b,
    const float* __restrict__ dm_w, const float* __restrict__ dm_b,
    const float* __restrict__ td_w)
{
    const int bx = blockIdx.x;
    if (bx == SPLIT_BLKS - 1) {               // prep block
        const int l = threadIdx.x;
        if (l < 32) {
            float ct = 0.f, cd = 0.f;
            bool z = true;
            #pragma unroll
            for (int m = l; m < 64; m += 32) {
                z = z && (tm_b[m] == 0.f) && (dm_b[m] == 0.f);
                ct += (0.5f * LOG2E) * td_w[m] * fmaxf(tm_w[m], 0.f);
                cd += (0.5f * LOG2E) * td_w[m] * fmaxf(dm_w[m], 0.f);
            }
            unsigned bz = __ballot_sync(0xffffffffu, z);
            #pragma unroll
            for (int o = 16; o; o >>= 1) {
                ct += __shfl_xor_sync(0xffffffffu, ct, o);
                cd += __shfl_xor_sync(0xffffffffu, cd, o);
            }
            if (l == 0) { g_Ct = ct; g_Cd = cd; g_bzero = (bz == 0xffffffffu); }
        }
        return;
    }

    const float* s;
    __half* dst;
    size_t off;
    if (bx < 3 * IN_BLKS) {
        int ten = bx / IN_BLKS, rel = bx % IN_BLKS;
        s = ((ten == 0) ? Q : (ten == 1) ? K : V) + (size_t)rel * 1024;
        off = (size_t)ten * NELE + (size_t)rel * 1024;
        dst = inh;
    } else {
        int id = bx - 3 * IN_BLKS;
        int ten = id / W_BLKS, rel = id % W_BLKS;
        s = ((ten == 0) ? Wq : (ten == 1) ? Wk : (ten == 2) ? Wv : Wo)
            + (size_t)rel * 1024;
        off = (size_t)ten * DD + (size_t)rel * 1024;
        dst = wh;
    }
    const size_t si = (size_t)threadIdx.x * 4;
    float4 v = *(const float4*)&s[si];
    __half2 h01 = __floats2half2_rn(v.x, v.y);
    __half2 h23 = __floats2half2_rn(v.z, v.w);
    *(uint2*)&dst[off + si] = make_uint2(*(uint32_t*)&h01, *(uint32_t*)&h23);
}

// ---------------------------------------------------------------------------
// Templated GEMM: tile MT x 128, A fp16, 3-stage cp.async pipeline.
// MT=128: 8 warps 4m x 2n; MT=64: 8 warps 2m x 4n.
// For MT=128, blockIdx.z in 3..6 runs co-scheduled bias+mask CTAs.
// ---------------------------------------------------------------------------
#define AKP 40
#define BNP 136
#define BS (32*BNP)

template<int MT>
__global__ __launch_bounds__(256, 2) void gemm_planes(
    const __half* __restrict__ Ah_, const __half* __restrict__ Wh_,
    size_t aStride, size_t wStride,
    const float* __restrict__ b0v, const float* __restrict__ b1v, const float* __restrict__ b2v,
    float* __restrict__ C0,
    __half* __restrict__ H0, __half* __restrict__ H1, __half* __restrict__ H2,
    int M, int N, int K, float scale0, int fp16_out,
    const float* __restrict__ tmat, const float* __restrict__ dmat,
    const int*   __restrict__ mask,
    const float* __restrict__ tm_w, const float* __restrict__ tm_b,
    const float* __restrict__ dm_w, const float* __restrict__ dm_b,
    const float* __restrict__ td_w, const float* __restrict__ td_b)
{
    extern __shared__ __half gsm[];
    const int t = threadIdx.x;

    // =================== bias + mask CTAs (MT=128 launch only) ============
    if (MT == 128 && blockIdx.z >= 3) {
        const int cta = (blockIdx.z - 3) * 128 + blockIdx.y * 4 + blockIdx.x; // 0..511
        const float tdb = td_b[0] * LOG2E;
        const float E = 2.718281828459045f;
        const int bz = g_bzero;
        const float Ct = g_Ct, Cd = g_Cd;

        float* sp = (float*)gsm;
        if (!bz) {
            if (t < 64) {
                sp[0*64 + t] = tm_w[t];
                sp[1*64 + t] = tm_b[t];
                sp[2*64 + t] = dm_w[t];
                sp[3*64 + t] = dm_b[t];
                sp[4*64 + t] = td_w[t] * 0.5f * LOG2E;
            }
            __syncthreads();
        }

        #pragma unroll 2
        for (int i = 0; i < 8; i++) {
            const size_t base = (((size_t)cta * 8 + i) * 256 + t) * 4;
            float4 u  = *(const float4*)(tmat + base);
            float4 w4 = *(const float4*)(dmat + base);
            int4   mk = *(const int4*)(mask + base);

            float tv[4] = { 1.f / __logf(E + u.x), 1.f / __logf(E + u.y),
                            1.f / __logf(E + u.z), 1.f / __logf(E + u.w) };
            float dv[4] = { 1.f / __logf(E + w4.x), 1.f / __logf(E + w4.y),
                            1.f / __logf(E + w4.z), 1.f / __logf(E + w4.w) };
            float acc[4];
            if (bz) {
                #pragma unroll
                for (int e = 0; e < 4; e++)
                    acc[e] = fmaf(tv[e], Ct, fmaf(dv[e], Cd, tdb));
            } else {
                #pragma unroll
                for (int e = 0; e < 4; e++) acc[e] = tdb;
                #pragma unroll 8
                for (int m = 0; m < 64; m++) {
                    const float tw = sp[0*64 + m], tb = sp[1*64 + m];
                    const float dw = sp[2*64 + m], db = sp[3*64 + m];
                    const float ww = sp[4*64 + m];
                    #pragma unroll
                    for (int e = 0; e < 4; e++) {
                        float rt = fmaxf(tv[e] * tw + tb, 0.f);
                        float rd = fmaxf(dv[e] * dw + db, 0.f);
                        acc[e] += ww * (rt + rd);
                    }
                }
            }
            float4 o;
            o.x = (mk.x == 1) ? -1.5e9f : acc[0];
            o.y = (mk.y == 1) ? -1.5e9f : acc[1];
            o.z = (mk.z == 1) ? -1.5e9f : acc[2];
            o.w = (mk.w == 1) ? -1.5e9f : acc[3];
            *(float4*)(g_bias + base) = o;
        }
        return;
    }

    // =================== GEMM CTAs ===================
    constexpr int AS = MT * AKP;
    constexpr int WM = (MT == 128) ? 4 : 2;      // m-warps
    constexpr int NP = WM;                        // 16-wide n p-tiles per warp
    __half* Ahs = gsm;                            // [3][AS]
    __half* Bhs = gsm + 3 * AS;                   // [3][BS]

    const int z = blockIdx.z;
    const __half* Ah = Ah_ + (size_t)z * aStride;
    const __half* Wh = Wh_ + (size_t)z * wStride;
    const float* bias = (z == 0) ? b0v : (z == 1) ? b1v : b2v;
    __half* Ho = (z == 0) ? H0 : (z == 1) ? H1 : H2;
    const float osc = (z == 0) ? scale0 : 1.f;

    const int lane = t & 31, wid = t >> 5;
    const int warp_m = wid & (WM - 1), warp_n = wid / WM;
    const int m_w = warp_m * 32, n_w = warp_n * (16 * WM);
    const int bm = blockIdx.y * MT, bn = blockIdx.x * 128;
    const int gid = lane >> 2, tig = lane & 3;
    const int m_idx = lane >> 3, rin = lane & 7;

    float acc[2][2 * NP][4];
    #pragma unroll
    for (int mt = 0; mt < 2; mt++)
        #pragma unroll
        for (int nt = 0; nt < 2 * NP; nt++)
            #pragma unroll
            for (int e = 0; e < 4; e++) acc[mt][nt][e] = 0.f;

    auto issue = [&](int st, int k0) {
        #pragma unroll
        for (int r = 0; r < MT / 64; r++) {
            int c = t + r * 256;
            int arow = c >> 2, ak = (c & 3) * 8;
            size_t ga = (size_t)(bm + arow) * K + k0 + ak;
            cpa16((uint32_t)__cvta_generic_to_shared(&Ahs[st * AS + arow * AKP + ak]), &Ah[ga]);
        }
        #pragma unroll
        for (int r = 0; r < 2; r++) {
            int c = t + r * 256;
            int krow = c >> 4, nc = (c & 15) * 8;
            size_t gb = (size_t)(k0 + krow) * N + bn + nc;
            cpa16((uint32_t)__cvta_generic_to_shared(&Bhs[st * BS + krow * BNP + nc]), &Wh[gb]);
        }
    };

    // 3-stage pipeline prologue
    issue(0, 0);
    cp_commit();
    issue(1, 32);
    cp_commit();

    const int NIT = K / 32;
    int st = 0;
    for (int it = 0; it < NIT; it++) {
        if (it + 2 < NIT) {
            int s2 = st + 2; if (s2 >= 3) s2 -= 3;
            issue(s2, (it + 2) * 32);
            cp_commit();
            cp_wait<2>();
        } else if (it + 1 < NIT) {
            cp_wait<1>();
        } else {
            cp_wait<0>();
        }
        __syncthreads();

        #pragma unroll
        for (int kb = 0; kb < 32; kb += 16) {
            uint32_t af[2][4];
            #pragma unroll
            for (int mt = 0; mt < 2; mt++) {
                const int arow = m_w + mt * 16 + (lane & 15);
                const int acol = kb + ((lane >> 4) << 3);
                ldsm_x4(af[mt][0], af[mt][1], af[mt][2], af[mt][3],
                        (uint32_t)__cvta_generic_to_shared(&Ahs[st * AS + arow * AKP + acol]));
            }
            #pragma unroll
            for (int p = 0; p < NP; p++) {
                const int brow = kb + ((m_idx & 1) << 3) + rin;
                const int bcol = n_w + p * 16 + ((m_idx >> 1) << 3);
                uint32_t bh0, bh1, bh2, bh3;
                ldsm_x4_t(bh0, bh1, bh2, bh3,
                    (uint32_t)__cvta_generic_to_shared(&Bhs[st * BS + brow * BNP + bcol]));
                #pragma unroll
                for (int mt = 0; mt < 2; mt++) {
                    mma_f16(acc[mt][2*p], af[mt][0], af[mt][1],
                            af[mt][2], af[mt][3], bh0, bh1);
                    mma_f16(acc[mt][2*p+1], af[mt][0], af[mt][1],
                            af[mt][2], af[mt][3], bh2, bh3);
                }
            }
        }
        __syncthreads();
        st = (st + 1 == 3) ? 0 : st + 1;
    }

    // ---- epilogue
    #pragma unroll
    for (int mt = 0; mt < 2; mt++) {
        const int row0 = bm + m_w + mt * 16 + gid;
        #pragma unroll
        for (int nt = 0; nt < 2 * NP; nt++) {
            const int col = bn + n_w + nt * 8 + tig * 2;
            float2 bb = *(const float2*)&bias[col];
            float v0 = (acc[mt][nt][0] + bb.x) * osc;
            float v1 = (acc[mt][nt][1] + bb.y) * osc;
            float v2 = (acc[mt][nt][2] + bb.x) * osc;
            float v3 = (acc[mt][nt][3] + bb.y) * osc;
            if (fp16_out) {
                __half2 h01 = __floats2half2_rn(v0, v1);
                __half2 h23 = __floats2half2_rn(v2, v3);
                *(__half2*)&Ho[(size_t)row0 * N + col]       = h01;
                *(__half2*)&Ho[(size_t)(row0 + 8) * N + col] = h23;
            } else {
                *(float2*)&C0[(size_t)row0 * N + col]       = make_float2(v0, v1);
                *(float2*)&C0[(size_t)(row0 + 8) * N + col] = make_float2(v2, v3);
            }
        }
    }
}

#define GSMEM_QKV ((3*(128*AKP) + 3*BS) * 2)   // 56832 B
#define GSMEM_O   ((3*(64*AKP)  + 3*BS) * 2)   // 41472 B

// ---------------------------------------------------------------------------
// Flash attention, pure fp16 TC, log2-domain softmax, smem-staged bias
// (block-wide staging, R12 layout). Epilogue -> single fp16 plane.
// ---------------------------------------------------------------------------
#define PS 72
#define PE (64*PS)
#define BSS 68
#define KV0 8704
#define SMEM_ATTN ((KV0 + 4*PE)*2)   // 54272 bytes

__global__ __launch_bounds__(128, 4) void attn_f16()
{
    extern __shared__ __half sm[];
    float* biasS = (float*)sm;

    const int qt = blockIdx.x, h = blockIdx.y, b = blockIdx.z;
    const int t = threadIdx.x;
    const int w = t >> 5, lane = t & 31;
    const int gid = lane >> 2, tig = lane & 3;
    const int q0 = qt * 64, hoff = h * DK_;
    const int tr = w * 16 + gid;
    const int m_idx = lane >> 3, rin = lane & 7;

    #pragma unroll
    for (int i = 0; i < 4; i++) {
        int c = t + i * 128;
        int row = c >> 3, col = (c & 7) * 8;
        size_t gq = (size_t)(b * S_ + q0 + row) * D_ + hoff + col;
        size_t gk = (size_t)(b * S_ + row) * D_ + hoff + col;
        uint32_t so = row * PS + col;
        cpa16((uint32_t)__cvta_generic_to_shared(&sm[so]),            &g_qh[gq]);
        cpa16((uint32_t)__cvta_generic_to_shared(&sm[KV0 + so]),      &g_kh[gk]);
        cpa16((uint32_t)__cvta_generic_to_shared(&sm[KV0 + PE + so]), &g_vh[gk]);
    }
    cp_commit();
    cp_wait<0>();
    __syncthreads();

    uint32_t qf[4][4];
    #pragma unroll
    for (int d8 = 0; d8 < 4; d8++) {
        uint32_t a = (uint32_t)__cvta_generic_to_shared(
            &sm[(w * 16 + (lane & 15)) * PS + d8 * 16 + ((lane >> 4) << 3)]);
        ldsm_x4(qf[d8][0], qf[d8][1], qf[d8][2], qf[d8][3], a);
    }
    __syncthreads();   // Q plane dead -> bias buffer

    float m0 = -1e30f, m1 = -1e30f, l0 = 0.f, l1 = 0.f;
    float oacc[8][4];
    #pragma unroll
    for (int nt = 0; nt < 8; nt++)
        #pragma unroll
        for (int e = 0; e < 4; e++) oacc[nt][e] = 0.f;

    for (int kt = 0; kt < 16; kt++) {
        const int buf = kt & 1;

        // ---- issue bias(kt) copy (group B_kt)
        #pragma unroll
        for (int i = 0; i < 8; i++) {
            int idx = t + i * 128;
            int row = idx >> 4, c4 = (idx & 15) << 2;
            cpa16((uint32_t)__cvta_generic_to_shared(&biasS[row * BSS + c4]),
                  &g_bias[((size_t)(b * S_ + q0 + row)) * S_ + kt * 64 + c4]);
        }
        cp_commit();

        // ---- issue KV(kt+1), wait KV(kt)
        if (kt < 15) {
            const int k1 = (kt + 1) * 64;
            const int KBn = KV0 + (buf ^ 1) * 2 * PE;
            #pragma unroll
            for (int i = 0; i < 4; i++) {
                int c = t + i * 128;
                int row = c >> 3, col = (c & 7) * 8;
                size_t g = (size_t)(b * S_ + k1 + row) * D_ + hoff + col;
                uint32_t so = row * PS + col;
                cpa16((uint32_t)__cvta_generic_to_shared(&sm[KBn + so]),      &g_kh[g]);
                cpa16((uint32_t)__cvta_generic_to_shared(&sm[KBn + PE + so]), &g_vh[g]);
            }
            cp_commit();
            cp_wait<2>();
        } else {
            cp_wait<1>();
        }
        __syncthreads();

        const int KB = KV0 + buf * 2 * PE;

        // ---- scores S = Q @ K^T (log2-domain), single-term fp16
        float sacc[8][4];
        #pragma unroll
        for (int nt = 0; nt < 8; nt++)
            #pragma unroll
            for (int e = 0; e < 4; e++) sacc[nt][e] = 0.f;

        #pragma unroll
        for (int d8 = 0; d8 < 4; d8++) {
            #pragma unroll
            for (int p = 0; p < 4; p++) {
                uint32_t boff = (p * 16 + ((m_idx & 1) << 3) + rin) * PS
                              + d8 * 16 + ((m_idx >> 1) << 3);
                uint32_t kh0, kh1, kh2, kh3;
                ldsm_x4(kh0, kh1, kh2, kh3,
                        (uint32_t)__cvta_generic_to_shared(&sm[KB + boff]));
                mma_f16(sacc[2*p],   qf[d8][0], qf[d8][1], qf[d8][2], qf[d8][3], kh0, kh2);
                mma_f16(sacc[2*p+1], qf[d8][0], qf[d8][1], qf[d8][2], qf[d8][3], kh1, kh3);
            }
        }

        // ---- bias now resident in smem
        if (kt < 15) { cp_wait<1>(); } else { cp_wait<0>(); }
        __syncthreads();

        float mx0 = -1e30f, mx1 = -1e30f;
        #pragma unroll
        for (int nt = 0; nt < 8; nt++) {
            float2 ba = *(const float2*)&biasS[tr * BSS + nt * 8 + tig * 2];
            float2 bb = *(const float2*)&biasS[(tr + 8) * BSS + nt * 8 + tig * 2];
            sacc[nt][0] += ba.x;
            sacc[nt][1] += ba.y;
            sacc[nt][2] += bb.x;
            sacc[nt][3] += bb.y;
            mx0 = fmaxf(mx0, fmaxf(sacc[nt][0], sacc[nt][1]));
            mx1 = fmaxf(mx1, fmaxf(sacc[nt][2], sacc[nt][3]));
        }
        mx0 = fmaxf(mx0, __shfl_xor_sync(0xffffffffu, mx0, 1));
        mx0 = fmaxf(mx0, __shfl_xor_sync(0xffffffffu, mx0, 2));
        mx1 = fmaxf(mx1, __shfl_xor_sync(0xffffffffu, mx1, 1));
        mx1 = fmaxf(mx1, __shfl_xor_sync(0xffffffffu, mx1, 2));

        const float mn0 = fmaxf(m0, mx0), mn1 = fmaxf(m1, mx1);
        const float c0 = ex2f(m0 - mn0), c1 = ex2f(m1 - mn1);
        m0 = mn0; m1 = mn1;

        float rs0 = 0.f, rs1 = 0.f;
        #pragma unroll
        for (int nt = 0; nt < 8; nt++) {
            sacc[nt][0] = ex2f(sacc[nt][0] - mn0);
            sacc[nt][1] = ex2f(sacc[nt][1] - mn0);
            sacc[nt][2] = ex2f(sacc[nt][2] - mn1);
            sacc[nt][3] = ex2f(sacc[nt][3] - mn1);
            rs0 += sacc[nt][0] + sacc[nt][1];
            rs1 += sacc[nt][2] + sacc[nt][3];
        }
        rs0 += __shfl_xor_sync(0xffffffffu, rs0, 1);
        rs0 += __shfl_xor_sync(0xffffffffu, rs0, 2);
        rs1 += __shfl_xor_sync(0xffffffffu, rs1, 1);
        rs1 += __shfl_xor_sync(0xffffffffu, rs1, 2);

        l0 = l0 * c0 + rs0;
        l1 = l1 * c1 + rs1;
        #pragma unroll
        for (int nt = 0; nt < 8; nt++) {
            oacc[nt][0] *= c0; oacc[nt][1] *= c0;
            oacc[nt][2] *= c1; oacc[nt][3] *= c1;
        }

        // ---- pack P into fp16 A-fragments (registers only)
        uint32_t pa[4][4];
        #pragma unroll
        for (int j8 = 0; j8 < 4; j8++) {
            const float* sA = sacc[2 * j8];
            const float* sB = sacc[2 * j8 + 1];
            __half2 hh;
            hh = __floats2half2_rn(sA[0], sA[1]); pa[j8][0] = *(uint32_t*)&hh;
            hh = __floats2half2_rn(sA[2], sA[3]); pa[j8][1] = *(uint32_t*)&hh;
            hh = __floats2half2_rn(sB[0], sB[1]); pa[j8][2] = *(uint32_t*)&hh;
            hh = __floats2half2_rn(sB[2], sB[3]); pa[j8][3] = *(uint32_t*)&hh;
        }

        // ---- O += P @ V : single-term fp16, V via ldmatrix.x4.trans
        #pragma unroll
        for (int j8 = 0; j8 < 4; j8++) {
            #pragma unroll
            for (int p = 0; p < 4; p++) {
                uint32_t boff = (j8 * 16 + ((m_idx & 1) << 3) + rin) * PS
                              + p * 16 + ((m_idx >> 1) << 3);
                uint32_t vh0, vh1, vh2, vh3;
                ldsm_x4_t(vh0, vh1, vh2, vh3,
                          (uint32_t)__cvta_generic_to_shared(&sm[KB + PE + boff]));
                mma_f16(oacc[2*p],   pa[j8][0], pa[j8][1], pa[j8][2], pa[j8][3], vh0, vh1);
                mma_f16(oacc[2*p+1], pa[j8][0], pa[j8][1], pa[j8][2], pa[j8][3], vh2, vh3);
            }
        }
        __syncthreads();   // KV buf + bias reads done before next overwrite
    }

    // ---- epilogue: normalize, write single fp16 plane [B,S,D]
    const float inv0 = 1.f / l0, inv1 = 1.f / l1;
    const size_t o0 = (size_t)(b * S_ + q0 + tr) * D_ + hoff;
    const size_t o1 = o0 + (size_t)8 * D_;
    #pragma unroll
    for (int nt = 0; nt < 8; nt++) {
        const int coff = nt * 8 + tig * 2;
        __half2 h01 = __floats2half2_rn(oacc[nt][0] * inv0, oacc[nt][1] * inv0);
        __half2 h23 = __floats2half2_rn(oacc[nt][2] * inv1, oacc[nt][3] * inv1);
        *(__half2*)&g_oh[o0 + coff] = h01;
        *(__half2*)&g_oh[o1 + coff] = h23;
    }
}

// ---------------------------------------------------------------------------
extern "C" void kernel_launch(void* const* d_in, const int* in_sizes, int n_in,
                              void* d_out, int out_size)
{
    const float* Q     = (const float*)d_in[0];
    const float* K     = (const float*)d_in[1];
    const float* V     = (const float*)d_in[2];
    const float* tmat  = (const float*)d_in[3];
    const float* dmat  = (const float*)d_in[4];
    const int*   mask  = (const int*)  d_in[5];
    const float* Wq    = (const float*)d_in[6];
    const float* bq    = (const float*)d_in[7];
    const float* Wk    = (const float*)d_in[8];
    const float* bk    = (const float*)d_in[9];
    const float* Wv    = (const float*)d_in[10];
    const float* bv    = (const float*)d_in[11];
    const float* Wo    = (const float*)d_in[12];
    const float* bo    = (const float*)d_in[13];
    const float* tm_w  = (const float*)d_in[14];
    const float* tm_b  = (const float*)d_in[15];
    const float* dm_w  = (const float*)d_in[16];
    const float* dm_b  = (const float*)d_in[17];
    const float* td_w  = (const float*)d_in[18];
    const float* td_b  = (const float*)d_in[19];
    float* out = (float*)d_out;

    __half *inh, *wh, *oh, *qh, *kh, *vh;
    cudaGetSymbolAddress((void**)&inh, g_in_h);
    cudaGetSymbolAddress((void**)&wh,  g_w_h);
    cudaGetSymbolAddress((void**)&oh,  g_oh);
    cudaGetSymbolAddress((void**)&qh,  g_qh);
    cudaGetSymbolAddress((void**)&kh,  g_kh);
    cudaGetSymbolAddress((void**)&vh,  g_vh);

    // split inputs/weights to fp16 + prep coefficients, one launch
    split_all<<<SPLIT_BLKS, 256>>>(
        Q, K, V, Wq, Wk, Wv, Wo, inh, wh, tm_w, tm_b, dm_w, dm_b, td_w);

    cudaFuncSetAttribute(gemm_planes<128>,
                         cudaFuncAttributeMaxDynamicSharedMemorySize, GSMEM_QKV);
    cudaFuncSetAttribute(gemm_planes<64>,
                         cudaFuncAttributeMaxDynamicSharedMemorySize, GSMEM_O);

    // fused Q/K/V projections (z=0..2) + bias/mask CTAs (z=3..6) in ONE launch
    gemm_planes<128><<<dim3(D_ / 128, MTOT / 128, 7), 256, GSMEM_QKV>>>(
        inh, wh, (size_t)NELE, (size_t)DD,
        bq, bk, bv,
        out /*unused*/, qh, kh, vh,
        MTOT, D_, D_, 0.125f * LOG2E, 1,
        tmat, dmat, mask, tm_w, tm_b, dm_w, dm_b, td_w, td_b);

    cudaFuncSetAttribute(attn_f16,
                         cudaFuncAttributeMaxDynamicSharedMemorySize, SMEM_ATTN);
    attn_f16<<<dim3(S_ / 64, H_, B_), 128, SMEM_ATTN>>>();

    // output projection: single fp16 A (attn out), 64x128 tiles -> 256 CTAs
    gemm_planes<64><<<dim3(D_ / 128, MTOT / 64, 1), 256, GSMEM_O>>>(
        oh, wh + (size_t)3 * DD, 0, 0,
        bo, bo, bo,
        out, qh, kh, vh,
        MTOT, D_, D_, 1.f, 0,
        tmat, dmat, mask, tm_w, tm_b, dm_w, dm_b, td_w, td_b);
}